// round 1
// baseline (speedup 1.0000x reference)
#include <cuda_runtime.h>
#include <cuda_bf16.h>
#include <cfloat>
#include <cstdint>

// Problem constants (from metadata: inputs [16,8192,256] f32, embeddings [16,256,1024] f32)
#define NV 16
#define NN 8192
#define ND 256
#define NK 1024

#define TM 64            // rows per block
#define TN 64            // cols per chunk
#define MARGIN 0.05f     // top-2 gap below which we fp64-recheck

// ---------------- scratch (no allocations allowed) ----------------
__device__ float  g_wsq[NV * NK];            // ||w_k||^2 per (v,k)
__device__ float  g_Wt [(size_t)NV * NK * ND]; // embeddings transposed to [V][K][D] (16 MB)
__device__ int    g_idx[NV * NN];            // argmin index per row
__device__ double g_accum;                   // sum of (q-x)^2

// ---------------- f32x2 helpers (FFMA2: 2x fp32 FMA rate on sm_103a) ----------------
__device__ __forceinline__ unsigned long long pk(float lo, float hi) {
    unsigned long long r;
    asm("mov.b64 %0, {%1, %2};" : "=l"(r) : "f"(lo), "f"(hi));
    return r;
}
__device__ __forceinline__ void upk(unsigned long long v, float& lo, float& hi) {
    asm("mov.b64 {%0, %1}, %2;" : "=f"(lo), "=f"(hi) : "l"(v));
}
__device__ __forceinline__ void fma2(unsigned long long& d, unsigned long long a, unsigned long long b) {
    asm("fma.rn.f32x2 %0, %1, %2, %0;" : "+l"(d) : "l"(a), "l"(b));
}

// ---------------- prep: ||w||^2 (fp64 accum) + zero loss accumulator ----------------
__global__ void wsq_kernel(const float* __restrict__ E) {
    int t = blockIdx.x * 256 + threadIdx.x;       // 0..16383
    int v = t >> 10, k = t & (NK - 1);
    const float* p = E + (size_t)v * ND * NK + k;
    double s = 0.0;
    #pragma unroll 8
    for (int d = 0; d < ND; ++d) {
        float w = p[(size_t)d * NK];
        s += (double)w * (double)w;
    }
    g_wsq[t] = (float)s;
    if (t == 0) g_accum = 0.0;
}

// ---------------- prep: transpose embeddings [V][D][K] -> [V][K][D] ----------------
__global__ void transpose_kernel(const float* __restrict__ E) {
    __shared__ float t[32][33];
    int v  = blockIdx.z;
    int k0 = blockIdx.x * 32;
    int d0 = blockIdx.y * 32;
    int tx = threadIdx.x, ty = threadIdx.y;       // block (32,8)
    const float* Ev = E + (size_t)v * ND * NK;
    #pragma unroll
    for (int j = 0; j < 32; j += 8)
        t[ty + j][tx] = Ev[(size_t)(d0 + ty + j) * NK + k0 + tx];
    __syncthreads();
    float* Wv = g_Wt + (size_t)v * NK * ND;
    #pragma unroll
    for (int j = 0; j < 32; j += 8)
        Wv[(size_t)(k0 + ty + j) * ND + d0 + tx] = t[tx][ty + j];
}

// ---------------- fp64 exact score for recheck ----------------
__device__ double dscore(const float* __restrict__ xrow, const float* __restrict__ Ev, int k) {
    const float* wc = Ev + k;
    double dot = 0.0, ws = 0.0;
    #pragma unroll 4
    for (int d = 0; d < ND; ++d) {
        double w = (double)wc[(size_t)d * NK];
        dot += (double)xrow[d] * w;
        ws  += w * w;
    }
    return ws - 2.0 * dot;
}

__device__ __forceinline__ void top2_update(float s, int k, float& b, int& bi, float& sec, int& si) {
    if (s < b)        { sec = b; si = bi; b = s; bi = k; }
    else if (s < sec) { sec = s; si = k; }
}

// ---------------- main argmin GEMM kernel ----------------
// grid (NN/TM, NV), 256 threads, 128 KB dynamic smem (Xs[256][64] + Ws[256][64])
__global__ void __launch_bounds__(256, 1)
argmin_kernel(const float* __restrict__ X, const float* __restrict__ E) {
    extern __shared__ float sm[];
    float* Xs = sm;              // [d][r], stride TM
    float* Ws = sm + ND * TM;    // [d][c], stride TN

    const int v    = blockIdx.y;
    const int row0 = blockIdx.x * TM;
    const int tid  = threadIdx.x;
    const int tx   = tid & 15;   // col group (4 cols)
    const int ty   = tid >> 4;   // row group (4 rows)

    const float* Xv = X + ((size_t)v * NN + row0) * ND;
    const float* Ev = E + (size_t)v * ND * NK;

    // Load X tile transposed into smem. Lane index varies r -> conflict-free STS.
    #pragma unroll
    for (int i = 0; i < 16; ++i) {
        int f  = tid + i * 256;      // 4096 float4 total
        int r  = f & 63;
        int dq = f >> 6;
        float4 xv = *(const float4*)(Xv + (size_t)r * ND + dq * 4);
        Xs[(dq * 4 + 0) * TM + r] = xv.x;
        Xs[(dq * 4 + 1) * TM + r] = xv.y;
        Xs[(dq * 4 + 2) * TM + r] = xv.z;
        Xs[(dq * 4 + 3) * TM + r] = xv.w;
    }

    float best[4], second[4];
    int   bidx[4], sidx[4];
    #pragma unroll
    for (int r = 0; r < 4; ++r) { best[r] = FLT_MAX; second[r] = FLT_MAX; bidx[r] = 0; sidx[r] = 0; }

    const float* xp = Xs + ty * 4;
    const float* wp = Ws + tx * 4;

    for (int kc = 0; kc < NK / TN; ++kc) {
        const int k0 = kc * TN;
        __syncthreads();
        // Load W chunk [256][64]: contiguous 256B per 16-thread group -> coalesced
        #pragma unroll
        for (int j = 0; j < 16; ++j) {
            int d  = (tid >> 4) + j * 16;
            int c0 = (tid & 15) * 4;
            *(float4*)(Ws + d * TN + c0) = *(const float4*)(Ev + (size_t)d * NK + k0 + c0);
        }
        __syncthreads();

        unsigned long long acc[8];
        #pragma unroll
        for (int i = 0; i < 8; ++i) acc[i] = 0ULL;

        #pragma unroll 16
        for (int d = 0; d < ND; ++d) {
            float4 xv = *(const float4*)(xp + (d << 6));   // 4 rows at depth d (broadcast-friendly)
            float4 wv = *(const float4*)(wp + (d << 6));   // 4 cols at depth d
            unsigned long long x01 = pk(xv.x, xv.y);       // rows (0,1)
            unsigned long long x23 = pk(xv.z, xv.w);       // rows (2,3)
            unsigned long long w0 = pk(wv.x, wv.x);
            unsigned long long w1 = pk(wv.y, wv.y);
            unsigned long long w2 = pk(wv.z, wv.z);
            unsigned long long w3 = pk(wv.w, wv.w);
            fma2(acc[0], x01, w0); fma2(acc[1], x01, w1);
            fma2(acc[2], x01, w2); fma2(acc[3], x01, w3);
            fma2(acc[4], x23, w0); fma2(acc[5], x23, w1);
            fma2(acc[6], x23, w2); fma2(acc[7], x23, w3);
        }

        float4 wsqv = *(const float4*)(g_wsq + v * NK + k0 + tx * 4);
        const float wsq_a[4] = { wsqv.x, wsqv.y, wsqv.z, wsqv.w };
        #pragma unroll
        for (int rp = 0; rp < 2; ++rp) {
            #pragma unroll
            for (int c = 0; c < 4; ++c) {
                float lo, hi;
                upk(acc[rp * 4 + c], lo, hi);
                int kk = k0 + tx * 4 + c;
                float s0 = wsq_a[c] - 2.0f * lo;
                float s1 = wsq_a[c] - 2.0f * hi;
                top2_update(s0, kk, best[rp * 2 + 0], bidx[rp * 2 + 0], second[rp * 2 + 0], sidx[rp * 2 + 0]);
                top2_update(s1, kk, best[rp * 2 + 1], bidx[rp * 2 + 1], second[rp * 2 + 1], sidx[rp * 2 + 1]);
            }
        }
    }

    // Reduce top-2 across the 16 lanes (same ty) via xor shuffles (width 16 stays in-warp).
    const unsigned mask = 0xFFFFFFFFu;
    #pragma unroll
    for (int off = 1; off < 16; off <<= 1) {
        #pragma unroll
        for (int r = 0; r < 4; ++r) {
            float ob  = __shfl_xor_sync(mask, best[r],   off);
            int   obi = __shfl_xor_sync(mask, bidx[r],   off);
            float os  = __shfl_xor_sync(mask, second[r], off);
            int   osi = __shfl_xor_sync(mask, sidx[r],   off);
            bool takeo = (ob < best[r]) || (ob == best[r] && obi < bidx[r]);
            float lb  = takeo ? best[r] : ob;     // losing best
            int   lbi = takeo ? bidx[r] : obi;
            float ws_ = takeo ? os : second[r];   // winner's second
            int   wsi = takeo ? osi : sidx[r];
            if (takeo) { best[r] = ob; bidx[r] = obi; }
            if (ws_ < lb || (ws_ == lb && wsi < lbi)) { second[r] = ws_; sidx[r] = wsi; }
            else                                      { second[r] = lb;  sidx[r] = lbi; }
        }
    }

    if (tx == 0) {
        #pragma unroll
        for (int r = 0; r < 4; ++r) {
            int grow = row0 + ty * 4 + r;
            int kk = bidx[r];
            if (second[r] - best[r] < MARGIN) {
                // fp64 recheck between top-2 candidates -> effectively exact argmin
                const float* xrow = X + ((size_t)v * NN + grow) * ND;
                double sb = dscore(xrow, Ev, bidx[r]);
                double ss = dscore(xrow, Ev, sidx[r]);
                if (ss < sb || (ss == sb && sidx[r] < bidx[r])) kk = sidx[r];
            }
            g_idx[v * NN + grow] = kk;
        }
    }
}

// ---------------- gather + loss-sum kernel: 4 rows / 256-thread block ----------------
__global__ void __launch_bounds__(256)
gather_kernel(const float* __restrict__ X, float* __restrict__ out) {
    int R      = blockIdx.x * 4 + (threadIdx.x >> 6);   // global row
    int lane64 = threadIdx.x & 63;
    int k = g_idx[R];
    int v = R >> 13;                                    // /8192
    const float4* q4 = (const float4*)(g_Wt + ((size_t)v * NK + k) * ND) + lane64;
    const float4* x4 = (const float4*)(X + (size_t)R * ND) + lane64;
    float4 qv = *q4;
    float4 xv = *x4;
    ((float4*)(out + (size_t)R * ND))[lane64] = qv;

    float dx = qv.x - xv.x, dy = qv.y - xv.y, dz = qv.z - xv.z, dw = qv.w - xv.w;
    float s = dx * dx + dy * dy + dz * dz + dw * dw;

    #pragma unroll
    for (int off = 16; off > 0; off >>= 1)
        s += __shfl_down_sync(0xFFFFFFFFu, s, off);

    __shared__ float ps[8];
    int wid = threadIdx.x >> 5, lid = threadIdx.x & 31;
    if (lid == 0) ps[wid] = s;
    __syncthreads();
    if (threadIdx.x == 0) {
        float tot = 0.0f;
        #pragma unroll
        for (int i = 0; i < 8; ++i) tot += ps[i];
        atomicAdd(&g_accum, (double)tot);
    }
}

// ---------------- write loss into trailing output element(s) ----------------
__global__ void loss_kernel(float* __restrict__ out, long long out_size) {
    const long long VND = (long long)NV * NN * ND;
    double loss = 1.25 * g_accum / (double)VND;   // q_latent + 0.25 * e_latent (value-equal)
    for (long long i = VND + threadIdx.x; i < out_size; i += blockDim.x)
        out[i] = (float)loss;
}

extern "C" void kernel_launch(void* const* d_in, const int* in_sizes, int n_in,
                              void* d_out, int out_size) {
    const float* X = (const float*)d_in[0];   // inputs [16,8192,256]
    const float* E = (const float*)d_in[1];   // embeddings [16,256,1024]
    float* out = (float*)d_out;

    const int smem_bytes = (ND * TM + ND * TN) * (int)sizeof(float);  // 131072
    cudaFuncSetAttribute((const void*)argmin_kernel,
                         cudaFuncAttributeMaxDynamicSharedMemorySize, smem_bytes);

    wsq_kernel<<<64, 256>>>(E);
    transpose_kernel<<<dim3(NK / 32, ND / 32, NV), dim3(32, 8)>>>(E);
    argmin_kernel<<<dim3(NN / TM, NV), 256, smem_bytes>>>(X, E);
    gather_kernel<<<(NV * NN) / 4, 256>>>(X, out);
    loss_kernel<<<1, 32>>>(out, (long long)out_size);
}

// round 2
// speedup vs baseline: 1.0015x; 1.0015x over previous
#include <cuda_runtime.h>
#include <cuda_bf16.h>
#include <cfloat>
#include <cstdint>

// Problem constants (from metadata: inputs [16,8192,256] f32, embeddings [16,256,1024] f32)
#define NV 16
#define NN 8192
#define ND 256
#define NK 1024

#define TM 64            // rows per block
#define TN 64            // cols per chunk
#define MARGIN 0.05f     // top-2 gap below which we fp64-recheck

// ---------------- scratch (no allocations allowed) ----------------
__device__ float  g_wsq[NV * NK];            // ||w_k||^2 per (v,k)
__device__ float  g_Wt [(size_t)NV * NK * ND]; // embeddings transposed to [V][K][D] (16 MB)
__device__ int    g_idx[NV * NN];            // argmin index per row
__device__ double g_accum;                   // sum of (q-x)^2

// ---------------- f32x2 helpers (FFMA2: 2x fp32 FMA rate on sm_103a) ----------------
__device__ __forceinline__ unsigned long long pk(float lo, float hi) {
    unsigned long long r;
    asm("mov.b64 %0, {%1, %2};" : "=l"(r) : "f"(lo), "f"(hi));
    return r;
}
__device__ __forceinline__ void upk(unsigned long long v, float& lo, float& hi) {
    asm("mov.b64 {%0, %1}, %2;" : "=f"(lo), "=f"(hi) : "l"(v));
}
__device__ __forceinline__ void fma2(unsigned long long& d, unsigned long long a, unsigned long long b) {
    asm("fma.rn.f32x2 %0, %1, %2, %0;" : "+l"(d) : "l"(a), "l"(b));
}

// ---------------- prep: ||w||^2 (fp64 accum) + zero loss accumulator ----------------
__global__ void wsq_kernel(const float* __restrict__ E) {
    int t = blockIdx.x * 256 + threadIdx.x;       // 0..16383
    int v = t >> 10, k = t & (NK - 1);
    const float* p = E + (size_t)v * ND * NK + k;
    double s = 0.0;
    #pragma unroll 8
    for (int d = 0; d < ND; ++d) {
        float w = p[(size_t)d * NK];
        s += (double)w * (double)w;
    }
    g_wsq[t] = (float)s;
    if (t == 0) g_accum = 0.0;
}

// ---------------- prep: transpose embeddings [V][D][K] -> [V][K][D] ----------------
__global__ void transpose_kernel(const float* __restrict__ E) {
    __shared__ float t[32][33];
    int v  = blockIdx.z;
    int k0 = blockIdx.x * 32;
    int d0 = blockIdx.y * 32;
    int tx = threadIdx.x, ty = threadIdx.y;       // block (32,8)
    const float* Ev = E + (size_t)v * ND * NK;
    #pragma unroll
    for (int j = 0; j < 32; j += 8)
        t[ty + j][tx] = Ev[(size_t)(d0 + ty + j) * NK + k0 + tx];
    __syncthreads();
    float* Wv = g_Wt + (size_t)v * NK * ND;
    #pragma unroll
    for (int j = 0; j < 32; j += 8)
        Wv[(size_t)(k0 + ty + j) * ND + d0 + tx] = t[tx][ty + j];
}

// ---------------- fp64 exact score for recheck ----------------
__device__ double dscore(const float* __restrict__ xrow, const float* __restrict__ Ev, int k) {
    const float* wc = Ev + k;
    double dot = 0.0, ws = 0.0;
    #pragma unroll 4
    for (int d = 0; d < ND; ++d) {
        double w = (double)wc[(size_t)d * NK];
        dot += (double)xrow[d] * w;
        ws  += w * w;
    }
    return ws - 2.0 * dot;
}

__device__ __forceinline__ void top2_update(float s, int k, float& b, int& bi, float& sec, int& si) {
    if (s < b)        { sec = b; si = bi; b = s; bi = k; }
    else if (s < sec) { sec = s; si = k; }
}

// ---------------- main argmin GEMM kernel ----------------
// grid (NN/TM, NV), 256 threads, 128 KB dynamic smem (Xs[256][64] + Ws[256][64])
__global__ void __launch_bounds__(256, 1)
argmin_kernel(const float* __restrict__ X, const float* __restrict__ E) {
    extern __shared__ float sm[];
    float* Xs = sm;              // [d][r], stride TM
    float* Ws = sm + ND * TM;    // [d][c], stride TN

    const int v    = blockIdx.y;
    const int row0 = blockIdx.x * TM;
    const int tid  = threadIdx.x;
    const int tx   = tid & 15;   // col group (4 cols)
    const int ty   = tid >> 4;   // row group (4 rows)

    const float* Xv = X + ((size_t)v * NN + row0) * ND;
    const float* Ev = E + (size_t)v * ND * NK;

    // Load X tile transposed into smem. Lane index varies r -> conflict-free STS.
    #pragma unroll
    for (int i = 0; i < 16; ++i) {
        int f  = tid + i * 256;      // 4096 float4 total
        int r  = f & 63;
        int dq = f >> 6;
        float4 xv = *(const float4*)(Xv + (size_t)r * ND + dq * 4);
        Xs[(dq * 4 + 0) * TM + r] = xv.x;
        Xs[(dq * 4 + 1) * TM + r] = xv.y;
        Xs[(dq * 4 + 2) * TM + r] = xv.z;
        Xs[(dq * 4 + 3) * TM + r] = xv.w;
    }

    float best[4], second[4];
    int   bidx[4], sidx[4];
    #pragma unroll
    for (int r = 0; r < 4; ++r) { best[r] = FLT_MAX; second[r] = FLT_MAX; bidx[r] = 0; sidx[r] = 0; }

    const float* xp = Xs + ty * 4;
    const float* wp = Ws + tx * 4;

    for (int kc = 0; kc < NK / TN; ++kc) {
        const int k0 = kc * TN;
        __syncthreads();
        // Load W chunk [256][64]: contiguous 256B per 16-thread group -> coalesced
        #pragma unroll
        for (int j = 0; j < 16; ++j) {
            int d  = (tid >> 4) + j * 16;
            int c0 = (tid & 15) * 4;
            *(float4*)(Ws + d * TN + c0) = *(const float4*)(Ev + (size_t)d * NK + k0 + c0);
        }
        __syncthreads();

        unsigned long long acc[8];
        #pragma unroll
        for (int i = 0; i < 8; ++i) acc[i] = 0ULL;

        #pragma unroll 16
        for (int d = 0; d < ND; ++d) {
            float4 xv = *(const float4*)(xp + (d << 6));   // 4 rows at depth d (broadcast-friendly)
            float4 wv = *(const float4*)(wp + (d << 6));   // 4 cols at depth d
            unsigned long long x01 = pk(xv.x, xv.y);       // rows (0,1)
            unsigned long long x23 = pk(xv.z, xv.w);       // rows (2,3)
            unsigned long long w0 = pk(wv.x, wv.x);
            unsigned long long w1 = pk(wv.y, wv.y);
            unsigned long long w2 = pk(wv.z, wv.z);
            unsigned long long w3 = pk(wv.w, wv.w);
            fma2(acc[0], x01, w0); fma2(acc[1], x01, w1);
            fma2(acc[2], x01, w2); fma2(acc[3], x01, w3);
            fma2(acc[4], x23, w0); fma2(acc[5], x23, w1);
            fma2(acc[6], x23, w2); fma2(acc[7], x23, w3);
        }

        float4 wsqv = *(const float4*)(g_wsq + v * NK + k0 + tx * 4);
        const float wsq_a[4] = { wsqv.x, wsqv.y, wsqv.z, wsqv.w };
        #pragma unroll
        for (int rp = 0; rp < 2; ++rp) {
            #pragma unroll
            for (int c = 0; c < 4; ++c) {
                float lo, hi;
                upk(acc[rp * 4 + c], lo, hi);
                int kk = k0 + tx * 4 + c;
                float s0 = wsq_a[c] - 2.0f * lo;
                float s1 = wsq_a[c] - 2.0f * hi;
                top2_update(s0, kk, best[rp * 2 + 0], bidx[rp * 2 + 0], second[rp * 2 + 0], sidx[rp * 2 + 0]);
                top2_update(s1, kk, best[rp * 2 + 1], bidx[rp * 2 + 1], second[rp * 2 + 1], sidx[rp * 2 + 1]);
            }
        }
    }

    // Reduce top-2 across the 16 lanes (same ty) via xor shuffles (width 16 stays in-warp).
    const unsigned mask = 0xFFFFFFFFu;
    #pragma unroll
    for (int off = 1; off < 16; off <<= 1) {
        #pragma unroll
        for (int r = 0; r < 4; ++r) {
            float ob  = __shfl_xor_sync(mask, best[r],   off);
            int   obi = __shfl_xor_sync(mask, bidx[r],   off);
            float os  = __shfl_xor_sync(mask, second[r], off);
            int   osi = __shfl_xor_sync(mask, sidx[r],   off);
            bool takeo = (ob < best[r]) || (ob == best[r] && obi < bidx[r]);
            float lb  = takeo ? best[r] : ob;     // losing best
            int   lbi = takeo ? bidx[r] : obi;
            float ws_ = takeo ? os : second[r];   // winner's second
            int   wsi = takeo ? osi : sidx[r];
            if (takeo) { best[r] = ob; bidx[r] = obi; }
            if (ws_ < lb || (ws_ == lb && wsi < lbi)) { second[r] = ws_; sidx[r] = wsi; }
            else                                      { second[r] = lb;  sidx[r] = lbi; }
        }
    }

    if (tx == 0) {
        #pragma unroll
        for (int r = 0; r < 4; ++r) {
            int grow = row0 + ty * 4 + r;
            int kk = bidx[r];
            if (second[r] - best[r] < MARGIN) {
                // fp64 recheck between top-2 candidates -> effectively exact argmin
                const float* xrow = X + ((size_t)v * NN + grow) * ND;
                double sb = dscore(xrow, Ev, bidx[r]);
                double ss = dscore(xrow, Ev, sidx[r]);
                if (ss < sb || (ss == sb && sidx[r] < bidx[r])) kk = sidx[r];
            }
            g_idx[v * NN + grow] = kk;
        }
    }
}

// ---------------- gather + loss-sum kernel: 4 rows / 256-thread block ----------------
__global__ void __launch_bounds__(256)
gather_kernel(const float* __restrict__ X, float* __restrict__ out) {
    int R      = blockIdx.x * 4 + (threadIdx.x >> 6);   // global row
    int lane64 = threadIdx.x & 63;
    int k = g_idx[R];
    int v = R >> 13;                                    // /8192
    const float4* q4 = (const float4*)(g_Wt + ((size_t)v * NK + k) * ND) + lane64;
    const float4* x4 = (const float4*)(X + (size_t)R * ND) + lane64;
    float4 qv = *q4;
    float4 xv = *x4;
    ((float4*)(out + (size_t)R * ND))[lane64] = qv;

    float dx = qv.x - xv.x, dy = qv.y - xv.y, dz = qv.z - xv.z, dw = qv.w - xv.w;
    float s = dx * dx + dy * dy + dz * dz + dw * dw;

    #pragma unroll
    for (int off = 16; off > 0; off >>= 1)
        s += __shfl_down_sync(0xFFFFFFFFu, s, off);

    __shared__ float ps[8];
    int wid = threadIdx.x >> 5, lid = threadIdx.x & 31;
    if (lid == 0) ps[wid] = s;
    __syncthreads();
    if (threadIdx.x == 0) {
        float tot = 0.0f;
        #pragma unroll
        for (int i = 0; i < 8; ++i) tot += ps[i];
        atomicAdd(&g_accum, (double)tot);
    }
}

// ---------------- write loss into trailing output element(s) ----------------
__global__ void loss_kernel(float* __restrict__ out, long long out_size) {
    const long long VND = (long long)NV * NN * ND;
    double loss = 1.25 * g_accum / (double)VND;   // q_latent + 0.25 * e_latent (value-equal)
    for (long long i = VND + threadIdx.x; i < out_size; i += blockDim.x)
        out[i] = (float)loss;
}

extern "C" void kernel_launch(void* const* d_in, const int* in_sizes, int n_in,
                              void* d_out, int out_size) {
    const float* X = (const float*)d_in[0];   // inputs [16,8192,256]
    const float* E = (const float*)d_in[1];   // embeddings [16,256,1024]
    float* out = (float*)d_out;

    const int smem_bytes = (ND * TM + ND * TN) * (int)sizeof(float);  // 131072
    cudaFuncSetAttribute((const void*)argmin_kernel,
                         cudaFuncAttributeMaxDynamicSharedMemorySize, smem_bytes);

    wsq_kernel<<<64, 256>>>(E);
    transpose_kernel<<<dim3(NK / 32, ND / 32, NV), dim3(32, 8)>>>(E);
    argmin_kernel<<<dim3(NN / TM, NV), 256, smem_bytes>>>(X, E);
    gather_kernel<<<(NV * NN) / 4, 256>>>(X, out);
    loss_kernel<<<1, 32>>>(out, (long long)out_size);
}

// round 4
// speedup vs baseline: 1.4109x; 1.4088x over previous
#include <cuda_runtime.h>
#include <cuda_bf16.h>
#include <cfloat>
#include <cstdint>

#define NV 16
#define NN 8192
#define ND 256
#define NK 1024
#define MARGIN 0.05f

// ---- smem layout (bytes) ----
// A: 2 bufs x 2 planes x (128 rows x 144B) ; B same ; wsq 4KB ; merge 4KB
#define ROWB   144
#define PLB    18432            // 128*144
#define ABUF   0
#define BBUF   73728
#define WSQ_S  147456
#define MRG    151552
#define SMEM_TOTAL 155648

// ---- device globals (static scratch; allocation-free) ----
__device__ float g_wsq[NV * NK];
__device__ float g_Wt[(size_t)NV * NK * ND];                       // [V][K][D] fp32
__device__ __align__(256) __nv_bfloat16 g_Xsp[2][(size_t)NV * NN * ND]; // X planes
__device__ __align__(256) __nv_bfloat16 g_Wsp[2][(size_t)NV * NK * ND]; // Wt planes
__device__ int    g_idx[NV * NN];
__device__ double g_accum;

// ---- helpers ----
__device__ __forceinline__ uint32_t smem_u32(const void* p) {
    uint32_t a;
    asm("{ .reg .u64 t; cvta.to.shared.u64 t, %1; cvt.u32.u64 %0, t; }" : "=r"(a) : "l"(p));
    return a;
}
__device__ __forceinline__ void cpa16(uint32_t dst, const void* src) {
    asm volatile("cp.async.cg.shared.global [%0], [%1], 16;" :: "r"(dst), "l"(src));
}
#define CP_COMMIT() asm volatile("cp.async.commit_group;" ::: "memory")
#define CP_WAIT1()  asm volatile("cp.async.wait_group 1;" ::: "memory")
#define CP_WAIT0()  asm volatile("cp.async.wait_group 0;" ::: "memory")

__device__ __forceinline__ uint32_t lds32(uint32_t a) {
    uint32_t v; asm volatile("ld.shared.b32 %0, [%1];" : "=r"(v) : "r"(a)); return v;
}
__device__ __forceinline__ void mma16816(float* c, const uint32_t* a, const uint32_t* b) {
    asm volatile("mma.sync.aligned.m16n8k16.row.col.f32.bf16.bf16.f32 "
        "{%0,%1,%2,%3}, {%4,%5,%6,%7}, {%8,%9}, {%0,%1,%2,%3};"
        : "+f"(c[0]), "+f"(c[1]), "+f"(c[2]), "+f"(c[3])
        : "r"(a[0]), "r"(a[1]), "r"(a[2]), "r"(a[3]), "r"(b[0]), "r"(b[1]));
}
__device__ __forceinline__ void top2_update(float s, int k, float& b, int& bi, float& sec, int& si) {
    if (s < b)        { sec = b; si = bi; b = s; bi = k; }
    else if (s < sec) { sec = s; si = k; }
}

// ---- prep: ||w||^2 ----
__global__ void wsq_kernel(const float* __restrict__ E) {
    int t = blockIdx.x * 256 + threadIdx.x;
    int v = t >> 10, k = t & (NK - 1);
    const float* p = E + (size_t)v * ND * NK + k;
    double s = 0.0;
    #pragma unroll 8
    for (int d = 0; d < ND; ++d) { float w = p[(size_t)d * NK]; s += (double)w * (double)w; }
    g_wsq[t] = (float)s;
    if (t == 0) g_accum = 0.0;
}

// ---- prep: transpose E [V][D][K] -> g_Wt [V][K][D] ----
__global__ void transpose_kernel(const float* __restrict__ E) {
    __shared__ float t[32][33];
    int v = blockIdx.z, k0 = blockIdx.x * 32, d0 = blockIdx.y * 32;
    int tx = threadIdx.x, ty = threadIdx.y;
    const float* Ev = E + (size_t)v * ND * NK;
    #pragma unroll
    for (int j = 0; j < 32; j += 8) t[ty + j][tx] = Ev[(size_t)(d0 + ty + j) * NK + k0 + tx];
    __syncthreads();
    float* Wv = g_Wt + (size_t)v * NK * ND;
    #pragma unroll
    for (int j = 0; j < 32; j += 8) Wv[(size_t)(k0 + ty + j) * ND + d0 + tx] = t[tx][ty + j];
}

// ---- prep: bf16x2 plane splits ----
__device__ __forceinline__ void split2(float x, __nv_bfloat16& a, __nv_bfloat16& b) {
    a = __float2bfloat16_rn(x);
    b = __float2bfloat16_rn(x - __bfloat162float(a));
}
__global__ void convertX_kernel(const float* __restrict__ X) {
    size_t i2 = ((size_t)blockIdx.x * 256 + threadIdx.x) * 2;
    float2 x = *(const float2*)(X + i2);
    __nv_bfloat16 a0, a1, b0, b1;
    split2(x.x, a0, a1); split2(x.y, b0, b1);
    *(__nv_bfloat162*)(&g_Xsp[0][i2]) = __nv_bfloat162(a0, b0);
    *(__nv_bfloat162*)(&g_Xsp[1][i2]) = __nv_bfloat162(a1, b1);
}
__global__ void convertW_kernel() {
    size_t i2 = ((size_t)blockIdx.x * 256 + threadIdx.x) * 2;
    float2 x = *(const float2*)(g_Wt + i2);
    __nv_bfloat16 a0, a1, b0, b1;
    split2(x.x, a0, a1); split2(x.y, b0, b1);
    *(__nv_bfloat162*)(&g_Wsp[0][i2]) = __nv_bfloat162(a0, b0);
    *(__nv_bfloat162*)(&g_Wsp[1][i2]) = __nv_bfloat162(a1, b1);
}

// ---- exact fp64 rescoring for near-ties ----
__device__ double dscore(const float* __restrict__ xrow, const float* __restrict__ Ev, int k) {
    const float* wc = Ev + k;
    double dot = 0.0, ws = 0.0;
    #pragma unroll 4
    for (int d = 0; d < ND; ++d) {
        double w = (double)wc[(size_t)d * NK];
        dot += (double)xrow[d] * w;
        ws  += w * w;
    }
    return ws - 2.0 * dot;
}

// ---- main: HMMA GEMM + argmin ----
// grid (NN/128, NV), 256 threads = 8 warps (4M x 2N), warp tile 32x64.
__global__ void __launch_bounds__(256, 1)
gemm_argmin_kernel(const float* __restrict__ X, const float* __restrict__ E) {
    extern __shared__ char smem[];
    const uint32_t sb = smem_u32(smem);
    const int tid = threadIdx.x, lane = tid & 31, wid = tid >> 5;
    const int wm = wid & 3, wn = wid >> 2;
    const int g = lane >> 2, tg = lane & 3;
    const int v = blockIdx.y, row0 = blockIdx.x * 128;

    // wsq -> smem
    {
        float* sw = (float*)(smem + WSQ_S);
        #pragma unroll
        for (int q = 0; q < 4; ++q) sw[tid + q * 256] = g_wsq[v * NK + tid + q * 256];
    }

    // cp.async issue for iteration `it` (it = nc*4 + dc), buffer it&1
    auto issue = [&](int it) {
        int nc = it >> 2, dc = it & 3, buf = it & 1;
        size_t abase = ((size_t)v * NN + row0) * ND + dc * 64;
        size_t bbase = ((size_t)v * NK + nc * 128) * ND + dc * 64;
        #pragma unroll
        for (int j = 0; j < 8; ++j) {
            int q = tid * 8 + j;                 // 0..2047
            int p = q >> 10, r = (q >> 3) & 127, c = q & 7;
            cpa16(sb + ABUF + buf * 36864 + p * PLB + r * ROWB + c * 16,
                  (const char*)g_Xsp[p] + (abase + (size_t)r * ND) * 2 + c * 16);
            cpa16(sb + BBUF + buf * 36864 + p * PLB + r * ROWB + c * 16,
                  (const char*)g_Wsp[p] + (bbase + (size_t)r * ND) * 2 + c * 16);
        }
        CP_COMMIT();
    };

    float best[4], sec[4];
    int bi4[4], si4[4];
    #pragma unroll
    for (int s = 0; s < 4; ++s) { best[s] = FLT_MAX; sec[s] = FLT_MAX; bi4[s] = 0; si4[s] = 0; }

    issue(0);

    const float* sw = (const float*)(smem + WSQ_S);
    for (int nc = 0; nc < 8; ++nc) {
        float c[2][8][4];
        #pragma unroll
        for (int mf = 0; mf < 2; ++mf)
            #pragma unroll
            for (int nf = 0; nf < 8; ++nf)
                #pragma unroll
                for (int e = 0; e < 4; ++e) c[mf][nf][e] = 0.0f;

        for (int dc = 0; dc < 4; ++dc) {
            int it = nc * 4 + dc, buf = it & 1;
            if (it < 31) { issue(it + 1); CP_WAIT1(); } else { CP_WAIT0(); }
            __syncthreads();

            const uint32_t A0b = sb + ABUF + buf * 36864;
            const uint32_t B0b = sb + BBUF + buf * 36864;
            #pragma unroll
            for (int ks = 0; ks < 4; ++ks) {
                const uint32_t kb = ks * 32 + tg * 4;
                uint32_t A0[2][4], A1[2][4];
                #pragma unroll
                for (int mf = 0; mf < 2; ++mf) {
                    uint32_t ra = A0b + (wm * 32 + mf * 16 + g) * ROWB + kb;
                    A0[mf][0] = lds32(ra);            A0[mf][1] = lds32(ra + 8 * ROWB);
                    A0[mf][2] = lds32(ra + 16);       A0[mf][3] = lds32(ra + 8 * ROWB + 16);
                    uint32_t rb = ra + PLB;
                    A1[mf][0] = lds32(rb);            A1[mf][1] = lds32(rb + 8 * ROWB);
                    A1[mf][2] = lds32(rb + 16);       A1[mf][3] = lds32(rb + 8 * ROWB + 16);
                }
                uint32_t B0[8][2], B1[8][2];
                #pragma unroll
                for (int nf = 0; nf < 8; ++nf) {
                    uint32_t rb = B0b + (wn * 64 + nf * 8 + g) * ROWB + kb;
                    B0[nf][0] = lds32(rb);       B0[nf][1] = lds32(rb + 16);
                    B1[nf][0] = lds32(rb + PLB); B1[nf][1] = lds32(rb + PLB + 16);
                }
                #pragma unroll
                for (int mf = 0; mf < 2; ++mf)
                    #pragma unroll
                    for (int nf = 0; nf < 8; ++nf) mma16816(c[mf][nf], A0[mf], B0[nf]);
                #pragma unroll
                for (int mf = 0; mf < 2; ++mf)
                    #pragma unroll
                    for (int nf = 0; nf < 8; ++nf) mma16816(c[mf][nf], A0[mf], B1[nf]);
                #pragma unroll
                for (int mf = 0; mf < 2; ++mf)
                    #pragma unroll
                    for (int nf = 0; nf < 8; ++nf) mma16816(c[mf][nf], A1[mf], B0[nf]);
            }
            __syncthreads();
        }

        // score + per-thread top-2 (thread owns rows: slot = mf*2+h)
        #pragma unroll
        for (int mf = 0; mf < 2; ++mf)
            #pragma unroll
            for (int nf = 0; nf < 8; ++nf)
                #pragma unroll
                for (int e = 0; e < 4; ++e) {
                    int col  = nc * 128 + wn * 64 + nf * 8 + tg * 2 + (e & 1);
                    int slot = mf * 2 + (e >> 1);
                    float sc = sw[col] - 2.0f * c[mf][nf][e];
                    top2_update(sc, col, best[slot], bi4[slot], sec[slot], si4[slot]);
                }
    }

    // merge across the 4 lanes sharing a row (tg = 0..3)
    const unsigned m = 0xFFFFFFFFu;
    #pragma unroll
    for (int off = 1; off < 4; off <<= 1) {
        #pragma unroll
        for (int s = 0; s < 4; ++s) {
            float ob  = __shfl_xor_sync(m, best[s], off);
            int   obi = __shfl_xor_sync(m, bi4[s], off);
            float os  = __shfl_xor_sync(m, sec[s], off);
            int   osi = __shfl_xor_sync(m, si4[s], off);
            bool tko = (ob < best[s]) || (ob == best[s] && obi < bi4[s]);
            float lb  = tko ? best[s] : ob;
            int   lbi = tko ? bi4[s] : obi;
            float ws_ = tko ? os : sec[s];
            int   wsi = tko ? osi : si4[s];
            if (tko) { best[s] = ob; bi4[s] = obi; }
            if (ws_ < lb || (ws_ == lb && wsi < lbi)) { sec[s] = ws_; si4[s] = wsi; }
            else                                       { sec[s] = lb;  si4[s] = lbi; }
        }
    }

    float* mb  = (float*)(smem + MRG);
    float* ms  = (float*)(smem + MRG + 1024);
    int*   mbi = (int*)  (smem + MRG + 2048);
    int*   msi = (int*)  (smem + MRG + 3072);
    if (tg == 0) {
        #pragma unroll
        for (int s = 0; s < 4; ++s) {
            int rl = wm * 32 + (s >> 1) * 16 + g + (s & 1) * 8;
            mb [wn * 128 + rl] = best[s];
            ms [wn * 128 + rl] = sec[s];
            mbi[wn * 128 + rl] = bi4[s];
            msi[wn * 128 + rl] = si4[s];
        }
    }
    __syncthreads();

    if (tid < 128) {
        float b0 = mb[tid],       s0 = ms[tid];
        int   b0i = mbi[tid],     s0i = msi[tid];
        float b1 = mb[128 + tid], s1 = ms[128 + tid];
        int   b1i = mbi[128 + tid], s1i = msi[128 + tid];

        float B, S; int Bi, Si;
        bool t0 = (b0 < b1) || (b0 == b1 && b0i < b1i);
        if (t0) { B = b0; Bi = b0i; float o = b1; int oi = b1i;
                  if (s0 < o || (s0 == o && s0i < oi)) { S = s0; Si = s0i; } else { S = o; Si = oi; } }
        else    { B = b1; Bi = b1i; float o = b0; int oi = b0i;
                  if (s1 < o || (s1 == o && s1i < oi)) { S = s1; Si = s1i; } else { S = o; Si = oi; } }

        int grow = row0 + tid, kk = Bi;
        if (S - B < MARGIN) {
            const float* xrow = X + ((size_t)v * NN + grow) * ND;
            const float* Ev = E + (size_t)v * ND * NK;
            double sb2 = dscore(xrow, Ev, Bi);
            double ss2 = dscore(xrow, Ev, Si);
            if (ss2 < sb2 || (ss2 == sb2 && Si < Bi)) kk = Si;
        }
        g_idx[v * NN + grow] = kk;
    }
}

// ---- gather + loss ----
__global__ void __launch_bounds__(256)
gather_kernel(const float* __restrict__ X, float* __restrict__ out) {
    int R = blockIdx.x * 4 + (threadIdx.x >> 6);
    int lane64 = threadIdx.x & 63;
    int k = g_idx[R];
    int v = R >> 13;
    float4 qv = ((const float4*)(g_Wt + ((size_t)v * NK + k) * ND))[lane64];
    float4 xv = ((const float4*)(X + (size_t)R * ND))[lane64];
    ((float4*)(out + (size_t)R * ND))[lane64] = qv;

    float dx = qv.x - xv.x, dy = qv.y - xv.y, dz = qv.z - xv.z, dw = qv.w - xv.w;
    float s = dx * dx + dy * dy + dz * dz + dw * dw;
    #pragma unroll
    for (int off = 16; off > 0; off >>= 1) s += __shfl_down_sync(0xFFFFFFFFu, s, off);

    __shared__ float ps[8];
    int w = threadIdx.x >> 5, l = threadIdx.x & 31;
    if (l == 0) ps[w] = s;
    __syncthreads();
    if (threadIdx.x == 0) {
        float tot = 0.0f;
        #pragma unroll
        for (int i = 0; i < 8; ++i) tot += ps[i];
        atomicAdd(&g_accum, (double)tot);
    }
}

__global__ void loss_kernel(float* __restrict__ out, long long out_size) {
    const long long VND = (long long)NV * NN * ND;
    double loss = 1.25 * g_accum / (double)VND;
    for (long long i = VND + threadIdx.x; i < out_size; i += blockDim.x)
        out[i] = (float)loss;
}

extern "C" void kernel_launch(void* const* d_in, const int* in_sizes, int n_in,
                              void* d_out, int out_size) {
    const float* X = (const float*)d_in[0];
    const float* E = (const float*)d_in[1];
    float* out = (float*)d_out;

    cudaFuncSetAttribute((const void*)gemm_argmin_kernel,
                         cudaFuncAttributeMaxDynamicSharedMemorySize, SMEM_TOTAL);

    wsq_kernel<<<64, 256>>>(E);
    transpose_kernel<<<dim3(NK / 32, ND / 32, NV), dim3(32, 8)>>>(E);
    convertX_kernel<<<(int)(((size_t)NV * NN * ND) / 512), 256>>>(X);
    convertW_kernel<<<(int)(((size_t)NV * NK * ND) / 512), 256>>>();
    gemm_argmin_kernel<<<dim3(NN / 128, NV), 256, SMEM_TOTAL>>>(X, E);
    gather_kernel<<<(NV * NN) / 4, 256>>>(X, out);
    loss_kernel<<<1, 32>>>(out, (long long)out_size);
}

// round 5
// speedup vs baseline: 1.8610x; 1.3190x over previous
#include <cuda_runtime.h>
#include <cuda_fp16.h>
#include <cfloat>
#include <cstdint>

#define NV 16
#define NN 8192
#define ND 256
#define NK 1024
#define W1 0.26f          // coarse-score uncertainty window (2E)
#define MARGIN 0.05f      // fp32-exact pair-adjudication margin

// ---- smem layout (bytes): A 2 bufs x (128 x 144B), B same, wsq, merge ----
#define ROWB   144
#define TILB   18432          // 128*144
#define ABUF   0
#define BBUF   36864
#define WSQ_S  73728
#define MRG    77824          // top-3 merge: 2 halves x 128 x 3 (float + int)
#define SMEM_TOTAL 83968

// ---- device scratch ----
__device__ float  g_wsq[NV * NK];
__device__ float  g_Wt[(size_t)NV * NK * ND];                    // [V][K][D] fp32
__device__ __align__(256) __half g_Xh[(size_t)NV * NN * ND];     // X fp16
__device__ __align__(256) __half g_Wh[(size_t)NV * NK * ND];     // Wt fp16
__device__ int    g_idx[NV * NN];
__device__ int    g_fix_count;
__device__ int    g_fix_rows[NV * NN];
__device__ double g_accum;

// ---- helpers ----
__device__ __forceinline__ uint32_t smem_u32(const void* p) {
    uint32_t a;
    asm("{ .reg .u64 t; cvta.to.shared.u64 t, %1; cvt.u32.u64 %0, t; }" : "=r"(a) : "l"(p));
    return a;
}
__device__ __forceinline__ void cpa16(uint32_t dst, const void* src) {
    asm volatile("cp.async.cg.shared.global [%0], [%1], 16;" :: "r"(dst), "l"(src));
}
#define CP_COMMIT() asm volatile("cp.async.commit_group;" ::: "memory")
#define CP_WAIT1()  asm volatile("cp.async.wait_group 1;" ::: "memory")
#define CP_WAIT0()  asm volatile("cp.async.wait_group 0;" ::: "memory")
__device__ __forceinline__ uint32_t lds32(uint32_t a) {
    uint32_t v; asm volatile("ld.shared.b32 %0, [%1];" : "=r"(v) : "r"(a)); return v;
}
__device__ __forceinline__ void mma16816(float* c, const uint32_t* a, const uint32_t* b) {
    asm volatile("mma.sync.aligned.m16n8k16.row.col.f32.f16.f16.f32 "
        "{%0,%1,%2,%3}, {%4,%5,%6,%7}, {%8,%9}, {%0,%1,%2,%3};"
        : "+f"(c[0]), "+f"(c[1]), "+f"(c[2]), "+f"(c[3])
        : "r"(a[0]), "r"(a[1]), "r"(a[2]), "r"(a[3]), "r"(b[0]), "r"(b[1]));
}
// sorted-triple insertion with deterministic index tiebreak
__device__ __forceinline__ void ins3(float v, int i, float* a, int* ai) {
    if (v < a[0] || (v == a[0] && i < ai[0])) {
        a[2] = a[1]; ai[2] = ai[1]; a[1] = a[0]; ai[1] = ai[0]; a[0] = v; ai[0] = i;
    } else if (v < a[1] || (v == a[1] && i < ai[1])) {
        a[2] = a[1]; ai[2] = ai[1]; a[1] = v; ai[1] = i;
    } else if (v < a[2] || (v == a[2] && i < ai[2])) {
        a[2] = v; ai[2] = i;
    }
}

// ---- prep kernels ----
__global__ void wsq_kernel(const float* __restrict__ E) {
    int t = blockIdx.x * 256 + threadIdx.x;
    int v = t >> 10, k = t & (NK - 1);
    const float* p = E + (size_t)v * ND * NK + k;
    double s = 0.0;
    #pragma unroll 8
    for (int d = 0; d < ND; ++d) { float w = p[(size_t)d * NK]; s += (double)w * (double)w; }
    g_wsq[t] = (float)s;
    if (t == 0) { g_accum = 0.0; g_fix_count = 0; }
}

__global__ void transpose_kernel(const float* __restrict__ E) {
    __shared__ float t[32][33];
    int v = blockIdx.z, k0 = blockIdx.x * 32, d0 = blockIdx.y * 32;
    int tx = threadIdx.x, ty = threadIdx.y;
    const float* Ev = E + (size_t)v * ND * NK;
    #pragma unroll
    for (int j = 0; j < 32; j += 8) t[ty + j][tx] = Ev[(size_t)(d0 + ty + j) * NK + k0 + tx];
    __syncthreads();
    float* Wv = g_Wt + (size_t)v * NK * ND;
    #pragma unroll
    for (int j = 0; j < 32; j += 8) Wv[(size_t)(k0 + ty + j) * ND + d0 + tx] = t[tx][ty + j];
}

__global__ void convertX_kernel(const float* __restrict__ X) {
    size_t i2 = ((size_t)blockIdx.x * 256 + threadIdx.x) * 2;
    float2 x = *(const float2*)(X + i2);
    *(__half2*)(&g_Xh[i2]) = __floats2half2_rn(x.x, x.y);
}
__global__ void convertW_kernel() {
    size_t i2 = ((size_t)blockIdx.x * 256 + threadIdx.x) * 2;
    float2 x = *(const float2*)(g_Wt + i2);
    *(__half2*)(&g_Wh[i2]) = __floats2half2_rn(x.x, x.y);
}

// ---- exact fp64 score ----
__device__ double dscore(const float* __restrict__ xrow, const float* __restrict__ Ev, int k) {
    const float* wc = Ev + k;
    double dot = 0.0, ws = 0.0;
    #pragma unroll 4
    for (int d = 0; d < ND; ++d) {
        double w = (double)wc[(size_t)d * NK];
        dot += (double)xrow[d] * w;
        ws  += w * w;
    }
    return ws - 2.0 * dot;
}

// ---- main: single-plane fp16 HMMA + top-3 + windowed adjudication ----
// grid (NN/128, NV), 256 thr = 8 warps (4M x 2N), warp tile 32x64
__global__ void __launch_bounds__(256, 2)
gemm_argmin_kernel(const float* __restrict__ X, const float* __restrict__ E) {
    extern __shared__ char smem[];
    const uint32_t sb = smem_u32(smem);
    const int tid = threadIdx.x, lane = tid & 31, wid = tid >> 5;
    const int wm = wid & 3, wn = wid >> 2;
    const int g = lane >> 2, tg = lane & 3;
    const int v = blockIdx.y, row0 = blockIdx.x * 128;

    {
        float* sw = (float*)(smem + WSQ_S);
        #pragma unroll
        for (int q = 0; q < 4; ++q) sw[tid + q * 256] = g_wsq[v * NK + tid + q * 256];
    }

    auto issue = [&](int it) {
        int nc = it >> 2, dc = it & 3, buf = it & 1;
        size_t abase = ((size_t)v * NN + row0) * ND + dc * 64;
        size_t bbase = ((size_t)v * NK + nc * 128) * ND + dc * 64;
        #pragma unroll
        for (int j = 0; j < 4; ++j) {
            int q = tid * 4 + j;                // 0..1023 16B-chunks
            int r = q >> 3, c = q & 7;
            cpa16(sb + ABUF + buf * TILB + r * ROWB + c * 16,
                  (const char*)g_Xh + (abase + (size_t)r * ND) * 2 + c * 16);
            cpa16(sb + BBUF + buf * TILB + r * ROWB + c * 16,
                  (const char*)g_Wh + (bbase + (size_t)r * ND) * 2 + c * 16);
        }
        CP_COMMIT();
    };

    // per-thread top-3 per row-slot (4 slots)
    float tv[4][3]; int ti[4][3];
    #pragma unroll
    for (int s = 0; s < 4; ++s)
        #pragma unroll
        for (int j = 0; j < 3; ++j) { tv[s][j] = FLT_MAX; ti[s][j] = 0x7FFFFFFF; }

    issue(0);
    const float* sw = (const float*)(smem + WSQ_S);

    for (int nc = 0; nc < 8; ++nc) {
        float c[2][8][4];
        #pragma unroll
        for (int mf = 0; mf < 2; ++mf)
            #pragma unroll
            for (int nf = 0; nf < 8; ++nf)
                #pragma unroll
                for (int e = 0; e < 4; ++e) c[mf][nf][e] = 0.0f;

        for (int dc = 0; dc < 4; ++dc) {
            int it = nc * 4 + dc, buf = it & 1;
            if (it < 31) { issue(it + 1); CP_WAIT1(); } else { CP_WAIT0(); }
            __syncthreads();

            const uint32_t Ab = sb + ABUF + buf * TILB;
            const uint32_t Bb = sb + BBUF + buf * TILB;
            #pragma unroll
            for (int ks = 0; ks < 4; ++ks) {
                const uint32_t kb = ks * 32 + tg * 4;
                uint32_t A[2][4];
                #pragma unroll
                for (int mf = 0; mf < 2; ++mf) {
                    uint32_t ra = Ab + (wm * 32 + mf * 16 + g) * ROWB + kb;
                    A[mf][0] = lds32(ra);       A[mf][1] = lds32(ra + 8 * ROWB);
                    A[mf][2] = lds32(ra + 16);  A[mf][3] = lds32(ra + 8 * ROWB + 16);
                }
                uint32_t B[8][2];
                #pragma unroll
                for (int nf = 0; nf < 8; ++nf) {
                    uint32_t rb = Bb + (wn * 64 + nf * 8 + g) * ROWB + kb;
                    B[nf][0] = lds32(rb); B[nf][1] = lds32(rb + 16);
                }
                #pragma unroll
                for (int mf = 0; mf < 2; ++mf)
                    #pragma unroll
                    for (int nf = 0; nf < 8; ++nf) mma16816(c[mf][nf], A[mf], B[nf]);
            }
            __syncthreads();
        }

        #pragma unroll
        for (int mf = 0; mf < 2; ++mf)
            #pragma unroll
            for (int nf = 0; nf < 8; ++nf)
                #pragma unroll
                for (int e = 0; e < 4; ++e) {
                    int col  = nc * 128 + wn * 64 + nf * 8 + tg * 2 + (e & 1);
                    int slot = mf * 2 + (e >> 1);
                    float sc = sw[col] - 2.0f * c[mf][nf][e];
                    // fast top-3 insert (strict <, ascending k order -> deterministic)
                    float* a = tv[slot]; int* ai = ti[slot];
                    if (sc < a[2]) {
                        if (sc < a[1]) {
                            a[2] = a[1]; ai[2] = ai[1];
                            if (sc < a[0]) { a[1] = a[0]; ai[1] = ai[0]; a[0] = sc; ai[0] = col; }
                            else           { a[1] = sc; ai[1] = col; }
                        } else { a[2] = sc; ai[2] = col; }
                    }
                }
    }

    // merge top-3 across the 4 lanes sharing each row (xor over tg bits)
    const unsigned m = 0xFFFFFFFFu;
    #pragma unroll
    for (int off = 1; off < 4; off <<= 1) {
        #pragma unroll
        for (int s = 0; s < 4; ++s) {
            float ov[3]; int oi[3];
            #pragma unroll
            for (int j = 0; j < 3; ++j) {
                ov[j] = __shfl_xor_sync(m, tv[s][j], off);
                oi[j] = __shfl_xor_sync(m, ti[s][j], off);
            }
            #pragma unroll
            for (int j = 0; j < 3; ++j) ins3(ov[j], oi[j], tv[s], ti[s]);
        }
    }

    float* mv = (float*)(smem + MRG);          // [2][128][3]
    int*   mi = (int*)  (smem + MRG + 3072);
    if (tg == 0) {
        #pragma unroll
        for (int s = 0; s < 4; ++s) {
            int rl = wm * 32 + (s >> 1) * 16 + g + (s & 1) * 8;
            #pragma unroll
            for (int j = 0; j < 3; ++j) {
                mv[(wn * 128 + rl) * 3 + j] = tv[s][j];
                mi[(wn * 128 + rl) * 3 + j] = ti[s][j];
            }
        }
    }
    __syncthreads();

    if (tid < 128) {
        float a[3]; int ai[3];
        #pragma unroll
        for (int j = 0; j < 3; ++j) { a[j] = mv[tid * 3 + j]; ai[j] = mi[tid * 3 + j]; }
        #pragma unroll
        for (int j = 0; j < 3; ++j) ins3(mv[(128 + tid) * 3 + j], mi[(128 + tid) * 3 + j], a, ai);

        int grow = row0 + tid, kk = ai[0];
        float gap2 = a[1] - a[0], gap3 = a[2] - a[0];
        if (gap3 < W1) {
            int slot = atomicAdd(&g_fix_count, 1);
            g_fix_rows[slot] = v * NN + grow;          // full exact rescore later
        } else if (gap2 < W1) {
            const float* xrow = X + ((size_t)v * NN + grow) * ND;
            const float* Ev = E + (size_t)v * ND * NK;
            double sb2 = dscore(xrow, Ev, ai[0]);
            double ss2 = dscore(xrow, Ev, ai[1]);
            if (ss2 < sb2 || (ss2 == sb2 && ai[1] < ai[0])) kk = ai[1];
        }
        g_idx[v * NN + grow] = kk;
    }
}

// ---- exact full-row rescore for flagged rows (one block per row) ----
__global__ void __launch_bounds__(256)
fix_kernel(const float* __restrict__ X, const float* __restrict__ E) {
    __shared__ float xs[ND];
    __shared__ float wv[16];
    __shared__ int   wi[16];
    int cnt = g_fix_count;
    for (int f = blockIdx.x; f < cnt; f += gridDim.x) {
        int R = g_fix_rows[f];
        int v = R >> 13;
        __syncthreads();
        xs[threadIdx.x] = X[(size_t)R * ND + threadIdx.x];
        __syncthreads();

        float b = FLT_MAX, s = FLT_MAX; int bi = 0x7FFFFFFF, si = 0x7FFFFFFF;
        #pragma unroll
        for (int kk = 0; kk < 4; ++kk) {
            int k = threadIdx.x * 4 + kk;
            const float* w = g_Wt + ((size_t)v * NK + k) * ND;
            float dot = 0.0f;
            #pragma unroll 8
            for (int d = 0; d < ND; ++d) dot = fmaf(xs[d], w[d], dot);
            float sc = g_wsq[v * NK + k] - 2.0f * dot;
            if (sc < b || (sc == b && k < bi)) { s = b; si = bi; b = sc; bi = k; }
            else if (sc < s || (sc == s && k < si)) { s = sc; si = k; }
        }
        const unsigned m = 0xFFFFFFFFu;
        #pragma unroll
        for (int off = 1; off < 32; off <<= 1) {
            float ob = __shfl_xor_sync(m, b, off);  int obi = __shfl_xor_sync(m, bi, off);
            float os = __shfl_xor_sync(m, s, off);  int osi = __shfl_xor_sync(m, si, off);
            bool tko = (ob < b) || (ob == b && obi < bi);
            float lb = tko ? b : ob; int lbi = tko ? bi : obi;
            float ws_ = tko ? os : s; int wsi = tko ? osi : si;
            if (tko) { b = ob; bi = obi; }
            if (ws_ < lb || (ws_ == lb && wsi < lbi)) { s = ws_; si = wsi; }
            else                                      { s = lb;  si = lbi; }
        }
        int wrp = threadIdx.x >> 5;
        if ((threadIdx.x & 31) == 0) { wv[wrp * 2] = b; wv[wrp * 2 + 1] = s; wi[wrp * 2] = bi; wi[wrp * 2 + 1] = si; }
        __syncthreads();
        if (threadIdx.x == 0) {
            float B = FLT_MAX, S = FLT_MAX; int Bi = 0x7FFFFFFF, Si = 0x7FFFFFFF;
            for (int q = 0; q < 16; ++q) {
                float vq = wv[q]; int iq = wi[q];
                if (vq < B || (vq == B && iq < Bi)) { S = B; Si = Bi; B = vq; Bi = iq; }
                else if (vq < S || (vq == S && iq < Si)) { S = vq; Si = iq; }
            }
            int kk = Bi;
            if (S - B < MARGIN) {
                const float* Ev = E + (size_t)v * ND * NK;
                double sb2 = dscore(xs, Ev, Bi);
                double ss2 = dscore(xs, Ev, Si);
                if (ss2 < sb2 || (ss2 == sb2 && Si < Bi)) kk = Si;
            }
            g_idx[R] = kk;
        }
        __syncthreads();
    }
}

// ---- gather + loss ----
__global__ void __launch_bounds__(256)
gather_kernel(const float* __restrict__ X, float* __restrict__ out) {
    int R = blockIdx.x * 4 + (threadIdx.x >> 6);
    int lane64 = threadIdx.x & 63;
    int k = g_idx[R];
    int v = R >> 13;
    float4 qv = ((const float4*)(g_Wt + ((size_t)v * NK + k) * ND))[lane64];
    float4 xv = ((const float4*)(X + (size_t)R * ND))[lane64];
    ((float4*)(out + (size_t)R * ND))[lane64] = qv;

    float dx = qv.x - xv.x, dy = qv.y - xv.y, dz = qv.z - xv.z, dw = qv.w - xv.w;
    float s = dx * dx + dy * dy + dz * dz + dw * dw;
    #pragma unroll
    for (int off = 16; off > 0; off >>= 1) s += __shfl_down_sync(0xFFFFFFFFu, s, off);

    __shared__ float ps[8];
    int w = threadIdx.x >> 5, l = threadIdx.x & 31;
    if (l == 0) ps[w] = s;
    __syncthreads();
    if (threadIdx.x == 0) {
        float tot = 0.0f;
        #pragma unroll
        for (int i = 0; i < 8; ++i) tot += ps[i];
        atomicAdd(&g_accum, (double)tot);
    }
}

__global__ void loss_kernel(float* __restrict__ out, long long out_size) {
    const long long VND = (long long)NV * NN * ND;
    double loss = 1.25 * g_accum / (double)VND;
    for (long long i = VND + threadIdx.x; i < out_size; i += blockDim.x)
        out[i] = (float)loss;
}

extern "C" void kernel_launch(void* const* d_in, const int* in_sizes, int n_in,
                              void* d_out, int out_size) {
    const float* X = (const float*)d_in[0];
    const float* E = (const float*)d_in[1];
    float* out = (float*)d_out;

    cudaFuncSetAttribute((const void*)gemm_argmin_kernel,
                         cudaFuncAttributeMaxDynamicSharedMemorySize, SMEM_TOTAL);

    wsq_kernel<<<64, 256>>>(E);
    transpose_kernel<<<dim3(NK / 32, ND / 32, NV), dim3(32, 8)>>>(E);
    convertX_kernel<<<65536, 256>>>(X);
    convertW_kernel<<<8192, 256>>>();
    gemm_argmin_kernel<<<dim3(NN / 128, NV), 256, SMEM_TOTAL>>>(X, E);
    fix_kernel<<<1024, 256>>>(X, E);
    gather_kernel<<<(NV * NN) / 4, 256>>>(X, out);
    loss_kernel<<<1, 32>>>(out, (long long)out_size);
}